// round 8
// baseline (speedup 1.0000x reference)
#include <cuda_runtime.h>
#include <cstdint>

// EfficientSHRFFN — bit-exact semantics (locked in R4, rel_err == 0.0):
//   B=262144, NPOS=4, D=64; opcode=3, OP_START=16 -> op_active idx 19
//   NIB_A=0, NIB_B=1, RESULT=2
//   value f32 sum order: strided halving (t0+t2)+(t1+t3), products exact
//   astype(int64) under x64-disabled jax -> int32, float->int32 SATURATES
//   shifts/byte-extract in int32
//
// R7 perf change: ITEMS 4 -> 8 (front-batched MLP=8, grid 16384 -> 8192).
// No cache hints (R5 showed .cs regresses steady-state wallclock).

static constexpr int ROW_F4      = 64;        // float4s per row
static constexpr long long N_F4  = 16777216;  // total float4s
static constexpr int ITEMS       = 8;
static constexpr int THREADS     = 256;

__device__ __forceinline__ float compute_result(const float* __restrict__ in,
                                                long long f4_idx)
{
    long long row_base = (f4_idx >> 6) << 8;   // row * 256 floats

    float a0 = __ldg(in + row_base + 0);
    float a1 = __ldg(in + row_base + 64);
    float a2 = __ldg(in + row_base + 128);
    float a3 = __ldg(in + row_base + 192);
    float sh_f = __ldg(in + row_base + 1);      // NIB_B at pos 0
    float op   = __ldg(in + row_base + 19);     // OP_START + opcode

    // Strided-halving tree: (t0+t2) + (t1+t3); power-of-two products are exact.
    float t1 = a1 * 256.0f;
    float t2 = a2 * 65536.0f;
    float t3 = a3 * 16777216.0f;
    float val = __fadd_rn(__fadd_rn(a0, t2), __fadd_rn(t1, t3));

    int value_i = (int)val;                     // saturating cvt.rzi.s32.f32

    int shift = (int)sh_f;
    if (shift < 0)  shift = 0;
    if (shift > 31) shift = 31;

    int shifted = value_i >> shift;

    int p = (int)((f4_idx >> 4) & 3);           // byte position 0..3
    int byte = (shifted >> (8 * p)) & 255;

    return (float)byte * op;
}

__global__ void __launch_bounds__(THREADS)
shrffn_kernel(const float4* __restrict__ in4,
              const float*  __restrict__ in,
              float4* __restrict__ out4)
{
    long long base = (long long)blockIdx.x * (THREADS * ITEMS) + threadIdx.x;

    // Batched front loads: 8 independent 128-bit LDGs (MLP=8), default policy.
    float4 v[ITEMS];
#pragma unroll
    for (int i = 0; i < ITEMS; i++) {
        v[i] = in4[base + (long long)i * THREADS];
    }

#pragma unroll
    for (int i = 0; i < ITEMS; i++) {
        long long g = base + (long long)i * THREADS;
        int r4 = (int)(g & (ROW_F4 - 1));
        if ((r4 & 15) == 0) {                   // r4 in {0,16,32,48}: .z is RESULT
            v[i].z = compute_result(in, g);
        }
    }

#pragma unroll
    for (int i = 0; i < ITEMS; i++) {
        out4[base + (long long)i * THREADS] = v[i];
    }
}

extern "C" void kernel_launch(void* const* d_in, const int* in_sizes, int n_in,
                              void* d_out, int out_size)
{
    const float* x = (const float*)d_in[0];
    float* out = (float*)d_out;

    const int blocks = (int)(N_F4 / (THREADS * ITEMS));   // 8192, exact division

    shrffn_kernel<<<blocks, THREADS>>>((const float4*)x, x, (float4*)out);
}

// round 9
// speedup vs baseline: 1.0047x; 1.0047x over previous
#include <cuda_runtime.h>
#include <cstdint>

// EfficientSHRFFN — bit-exact semantics (locked in R4, rel_err == 0.0):
//   B=262144, NPOS=4, D=64; opcode=3, OP_START=16 -> op_active idx 19
//   NIB_A=0, NIB_B=1, RESULT=2
//   value f32 sum order: strided halving (t0+t2)+(t1+t3), products exact
//   astype(int64) under x64-disabled jax -> int32, float->int32 SATURATES
//   shifts/byte-extract in int32
//
// Perf history: ITEMS=1 ncu 81.8 | ITEMS=4/T256 ncu 74.6 wall 82.1 (best)
//   | ITEMS=8 ncu 75.9 occ 48.9% (reg pressure, reverted) | .cs hints regress wall.
// R9 change: ITEMS=4, THREADS 256 -> 512 (same regs/occ limit, half the CTAs,
// half the wave transitions).

static constexpr int ROW_F4      = 64;        // float4s per row
static constexpr long long N_F4  = 16777216;  // total float4s
static constexpr int ITEMS       = 4;
static constexpr int THREADS     = 512;

__device__ __forceinline__ float compute_result(const float* __restrict__ in,
                                                long long f4_idx)
{
    long long row_base = (f4_idx >> 6) << 8;   // row * 256 floats

    float a0 = __ldg(in + row_base + 0);
    float a1 = __ldg(in + row_base + 64);
    float a2 = __ldg(in + row_base + 128);
    float a3 = __ldg(in + row_base + 192);
    float sh_f = __ldg(in + row_base + 1);      // NIB_B at pos 0
    float op   = __ldg(in + row_base + 19);     // OP_START + opcode

    // Strided-halving tree: (t0+t2) + (t1+t3); power-of-two products are exact.
    float t1 = a1 * 256.0f;
    float t2 = a2 * 65536.0f;
    float t3 = a3 * 16777216.0f;
    float val = __fadd_rn(__fadd_rn(a0, t2), __fadd_rn(t1, t3));

    int value_i = (int)val;                     // saturating cvt.rzi.s32.f32

    int shift = (int)sh_f;
    if (shift < 0)  shift = 0;
    if (shift > 31) shift = 31;

    int shifted = value_i >> shift;

    int p = (int)((f4_idx >> 4) & 3);           // byte position 0..3
    int byte = (shifted >> (8 * p)) & 255;

    return (float)byte * op;
}

__global__ void __launch_bounds__(THREADS)
shrffn_kernel(const float4* __restrict__ in4,
              const float*  __restrict__ in,
              float4* __restrict__ out4)
{
    long long base = (long long)blockIdx.x * (THREADS * ITEMS) + threadIdx.x;

    // Batched front loads: 4 independent 128-bit LDGs (MLP=4), default policy.
    float4 v[ITEMS];
#pragma unroll
    for (int i = 0; i < ITEMS; i++) {
        v[i] = in4[base + (long long)i * THREADS];
    }

#pragma unroll
    for (int i = 0; i < ITEMS; i++) {
        long long g = base + (long long)i * THREADS;
        int r4 = (int)(g & (ROW_F4 - 1));
        if ((r4 & 15) == 0) {                   // r4 in {0,16,32,48}: .z is RESULT
            v[i].z = compute_result(in, g);
        }
    }

#pragma unroll
    for (int i = 0; i < ITEMS; i++) {
        out4[base + (long long)i * THREADS] = v[i];
    }
}

extern "C" void kernel_launch(void* const* d_in, const int* in_sizes, int n_in,
                              void* d_out, int out_size)
{
    const float* x = (const float*)d_in[0];
    float* out = (float*)d_out;

    const int blocks = (int)(N_F4 / (THREADS * ITEMS));   // 8192, exact division

    shrffn_kernel<<<blocks, THREADS>>>((const float4*)x, x, (float4*)out);
}